// round 5
// baseline (speedup 1.0000x reference)
#include <cuda_runtime.h>
#include <math.h>

#define BB 4
#define SS 2048
#define DD 1024
#define HH 16
#define HDIM 64

// Scratch (device globals: allocation-free per harness rules)
__device__ float g_base[(size_t)BB * SS * 3 * DD];   // [8192, 3072]
__device__ float g_hidden[(size_t)BB * SS * DD];     // [8192, 1024]
__device__ float g_ctrl[(size_t)BB * SS * 5 * HH];   // [8192, 80]
__device__ float g_ys[(size_t)BB * SS * DD];         // [8192, 1024]
__device__ float g_mf[(size_t)BB * HH * HDIM * HDIM];// fallback M_final scratch

// ---------------------------------------------------------------------------
// bf16x3 split-precision GEMM: C = act(A @ B + bias), fp32 in/out.
// a = a_hi + a_lo (bf16 each); C ~= Ah@Bh + Ah@Bl + Al@Bh (lo*lo ~2^-18 dropped)
// 128x128x16 tile, 256 threads, 8 warps (warp tile 32x64), mma.m16n8k16.bf16.
// smem: planes hi/lo, row stride 12 u32 (k-pairs), swizzle kp^(r&3)^((r>>3)&3)
// -> conflict-free fragment loads and stores (verified bank-disjoint).
// ---------------------------------------------------------------------------
#define TBM 128
#define TBN 128
#define TBK 16
#define XSTR 12
#define PLANE (TBM * XSTR)        // 1536 u32 per plane

__device__ __forceinline__ void split2(float a0, float a1,
                                       unsigned& hi, unsigned& lo) {
    // hi = pack(bf16(a1), bf16(a0)); lo = pack(bf16(a1-h1), bf16(a0-h0))
    asm("cvt.rn.bf16x2.f32 %0, %1, %2;" : "=r"(hi) : "f"(a1), "f"(a0));
    float h0 = __uint_as_float(hi << 16);
    float h1 = __uint_as_float(hi & 0xffff0000u);
    float r0 = a0 - h0, r1 = a1 - h1;
    asm("cvt.rn.bf16x2.f32 %0, %1, %2;" : "=r"(lo) : "f"(r1), "f"(r0));
}

__device__ __forceinline__ void mma_bf16(float* c, const unsigned* a,
                                         unsigned b0, unsigned b1) {
    asm volatile(
        "mma.sync.aligned.m16n8k16.row.col.f32.bf16.bf16.f32 "
        "{%0,%1,%2,%3}, {%4,%5,%6,%7}, {%8,%9}, {%0,%1,%2,%3};"
        : "+f"(c[0]), "+f"(c[1]), "+f"(c[2]), "+f"(c[3])
        : "r"(a[0]), "r"(a[1]), "r"(a[2]), "r"(a[3]), "r"(b0), "r"(b1));
}

__global__ __launch_bounds__(256) void gemm_bf16x3(
    const float* __restrict__ A, const float* __restrict__ B,
    const float* __restrict__ bias, float* __restrict__ C,
    int M, int N, int K, int act)
{
    __shared__ __align__(16) unsigned As[2][2 * PLANE]; // [buf][plane*1536 + idx]
    __shared__ __align__(16) unsigned Bs[2][2 * PLANE];

    int tid  = threadIdx.x;
    int lane = tid & 31;
    int warp = tid >> 5;
    int wm = warp >> 1, wn = warp & 1;
    int bm = blockIdx.y * TBM;
    int bn = blockIdx.x * TBN;

    // --- global load mappings ---
    // A: thread -> row=tid>>1 (0..127), k-half h=tid&1 (8 k each, 2 float4)
    int arow = tid >> 1, ah = tid & 1;
    const float* Aptr = A + (size_t)(bm + arow) * K + ah * 8;
    int xa = (arow & 3) ^ ((arow >> 3) & 3);
    int ast_base = arow * XSTR + 4 * ah;          // + (i ^ xa)
    // B: thread -> n=tid&127, k-half bh2=tid>>7 (kp base 4*bh2)
    int bnn = tid & 127, bh2 = tid >> 7;
    int gcol = bn + bnn;
    int xb = (bnn & 3) ^ ((bnn >> 3) & 3);
    int bst_base = bnn * XSTR + 4 * bh2;          // + (i ^ xb)

    // --- fragment load indices (precomputed; +4 gives the k+8 half) ---
    int fg = lane >> 2, ft = lane & 3;
    int idxA[2][2];                                // [mtile][row/row+8]
#pragma unroll
    for (int i = 0; i < 2; i++) {
#pragma unroll
        for (int d = 0; d < 2; d++) {
            int row = wm * 32 + i * 16 + d * 8 + fg;
            idxA[i][d] = row * XSTR + (ft ^ (row & 3) ^ ((row >> 3) & 3));
        }
    }
    int idxB[8];
#pragma unroll
    for (int j = 0; j < 8; j++) {
        int n = wn * 64 + j * 8 + fg;
        idxB[j] = n * XSTR + (ft ^ (n & 3) ^ ((n >> 3) & 3));
    }

    float acc[2][8][4];
#pragma unroll
    for (int i = 0; i < 2; i++)
#pragma unroll
        for (int j = 0; j < 8; j++)
#pragma unroll
            for (int l = 0; l < 4; l++) acc[i][j][l] = 0.f;

    // --- prologue: tile 0 -> buf 0 ---
    {
        float4 f0 = *(const float4*)Aptr;
        float4 f1 = *(const float4*)(Aptr + 4);
        unsigned hi, lo;
        split2(f0.x, f0.y, hi, lo);
        As[0][ast_base + (0 ^ xa)] = hi; As[0][PLANE + ast_base + (0 ^ xa)] = lo;
        split2(f0.z, f0.w, hi, lo);
        As[0][ast_base + (1 ^ xa)] = hi; As[0][PLANE + ast_base + (1 ^ xa)] = lo;
        split2(f1.x, f1.y, hi, lo);
        As[0][ast_base + (2 ^ xa)] = hi; As[0][PLANE + ast_base + (2 ^ xa)] = lo;
        split2(f1.z, f1.w, hi, lo);
        As[0][ast_base + (3 ^ xa)] = hi; As[0][PLANE + ast_base + (3 ^ xa)] = lo;
#pragma unroll
        for (int i = 0; i < 4; i++) {
            int k = 8 * bh2 + 2 * i;
            float b0 = (gcol < N) ? B[(size_t)k * N + gcol] : 0.f;
            float b1 = (gcol < N) ? B[(size_t)(k + 1) * N + gcol] : 0.f;
            split2(b0, b1, hi, lo);
            Bs[0][bst_base + (i ^ xb)] = hi;
            Bs[0][PLANE + bst_base + (i ^ xb)] = lo;
        }
    }
    __syncthreads();

    int iters = K / TBK;   // 64
    for (int it = 1; it <= iters; it++) {
        bool has = (it < iters);
        float4 f0, f1;
        float bg[8];
        if (has) {
            int k0 = it * TBK;
            f0 = *(const float4*)(Aptr + k0);
            f1 = *(const float4*)(Aptr + k0 + 4);
#pragma unroll
            for (int i = 0; i < 4; i++) {
                int k = k0 + 8 * bh2 + 2 * i;
                bg[2 * i]     = (gcol < N) ? B[(size_t)k * N + gcol] : 0.f;
                bg[2 * i + 1] = (gcol < N) ? B[(size_t)(k + 1) * N + gcol] : 0.f;
            }
        }

        // --- compute on buffer (it-1)&1 ---
        {
            const unsigned* Ab = As[(it - 1) & 1];
            const unsigned* Bb = Bs[(it - 1) & 1];
            unsigned ahf[2][4], alf[2][4];
#pragma unroll
            for (int i = 0; i < 2; i++) {
                ahf[i][0] = Ab[idxA[i][0]];
                ahf[i][1] = Ab[idxA[i][1]];
                ahf[i][2] = Ab[idxA[i][0] + 4];
                ahf[i][3] = Ab[idxA[i][1] + 4];
                alf[i][0] = Ab[PLANE + idxA[i][0]];
                alf[i][1] = Ab[PLANE + idxA[i][1]];
                alf[i][2] = Ab[PLANE + idxA[i][0] + 4];
                alf[i][3] = Ab[PLANE + idxA[i][1] + 4];
            }
#pragma unroll
            for (int j = 0; j < 8; j++) {
                unsigned bh0 = Bb[idxB[j]];
                unsigned bh1 = Bb[idxB[j] + 4];
                unsigned bl0 = Bb[PLANE + idxB[j]];
                unsigned bl1 = Bb[PLANE + idxB[j] + 4];
                mma_bf16(acc[0][j], ahf[0], bh0, bh1);   // hi*hi
                mma_bf16(acc[1][j], ahf[1], bh0, bh1);
                mma_bf16(acc[0][j], ahf[0], bl0, bl1);   // hi*lo
                mma_bf16(acc[1][j], ahf[1], bl0, bl1);
                mma_bf16(acc[0][j], alf[0], bh0, bh1);   // lo*hi
                mma_bf16(acc[1][j], alf[1], bh0, bh1);
            }
        }

        if (has) {
            int buf = it & 1;
            unsigned hi, lo;
            split2(f0.x, f0.y, hi, lo);
            As[buf][ast_base + (0 ^ xa)] = hi; As[buf][PLANE + ast_base + (0 ^ xa)] = lo;
            split2(f0.z, f0.w, hi, lo);
            As[buf][ast_base + (1 ^ xa)] = hi; As[buf][PLANE + ast_base + (1 ^ xa)] = lo;
            split2(f1.x, f1.y, hi, lo);
            As[buf][ast_base + (2 ^ xa)] = hi; As[buf][PLANE + ast_base + (2 ^ xa)] = lo;
            split2(f1.z, f1.w, hi, lo);
            As[buf][ast_base + (3 ^ xa)] = hi; As[buf][PLANE + ast_base + (3 ^ xa)] = lo;
#pragma unroll
            for (int i = 0; i < 4; i++) {
                split2(bg[2 * i], bg[2 * i + 1], hi, lo);
                Bs[buf][bst_base + (i ^ xb)] = hi;
                Bs[buf][PLANE + bst_base + (i ^ xb)] = lo;
            }
        }
        __syncthreads();
    }

    // --- epilogue (same C fragment layout as m16n8k8) ---
#pragma unroll
    for (int i = 0; i < 2; i++) {
        int row = bm + wm * 32 + i * 16 + fg;
#pragma unroll
        for (int j = 0; j < 8; j++) {
            int col = bn + wn * 64 + j * 8 + ft * 2;
            if (col < N) {
                float b0 = bias[col], b1 = bias[col + 1];
                float v0 = acc[i][j][0] + b0;
                float v1 = acc[i][j][1] + b1;
                float v2 = acc[i][j][2] + b0;
                float v3 = acc[i][j][3] + b1;
                if (act == 1) {
                    v0 = v0 / (1.f + __expf(-v0));
                    v1 = v1 / (1.f + __expf(-v1));
                    v2 = v2 / (1.f + __expf(-v2));
                    v3 = v3 / (1.f + __expf(-v3));
                }
                *(float2*)&C[(size_t)row * N + col] = make_float2(v0, v1);
                *(float2*)&C[(size_t)(row + 8) * N + col] = make_float2(v2, v3);
            }
        }
    }
}

// ---------------------------------------------------------------------------
// Sequential scan, cp.async pipelined (DEPTH=4, ~3-step prefetch cover).
// 128 blocks: (b*16+h)*2 + half; 128 threads: r=(tid>>2)+half*32, g=tid&3.
// ctrl coefficients folded as scalars (dots on raw k/q, scale after).
// ---------------------------------------------------------------------------
#define SDEPTH 4
#define SBUF 224   // floats per stage: k[0:64) v[64:128) q[128:192) c[192:197)

__device__ __forceinline__ void cpasync4(unsigned saddr, const float* gptr) {
    asm volatile("cp.async.ca.shared.global [%0], [%1], 4;"
                 :: "r"(saddr), "l"(gptr) : "memory");
}
__device__ __forceinline__ void cpcommit() {
    asm volatile("cp.async.commit_group;" ::: "memory");
}
__device__ __forceinline__ void cpwait2() {
    asm volatile("cp.async.wait_group 2;" ::: "memory");
}

__global__ __launch_bounds__(128) void scan_kernel(
    const float* __restrict__ base,    // [B,S,H,3,HD]
    const float* __restrict__ ctrl,    // [B,S,H,5]
    const float* __restrict__ memory0, // [B,H,HD,HD]
    float* __restrict__ ys,            // [B,S,D]
    float* __restrict__ mfinal)        // [B,H,HD,HD]
{
    __shared__ __align__(16) float sbuf[SDEPTH][SBUF];

    int bh   = blockIdx.x >> 1;
    int half = blockIdx.x & 1;
    int b = bh >> 4, h = bh & 15;
    int tid = threadIdx.x;
    int r = (tid >> 2) + half * 32;
    int g = tid & 3;

    float m[16];
    {
        const float* M0 = memory0 + (((size_t)bh * HDIM + r) * HDIM + g * 16);
#pragma unroll
        for (int jj = 0; jj < 16; jj++) m[jj] = M0[jj];
    }

    const float* bsrc = base + ((size_t)b * SS * HH + h) * 192;  // +s*3072
    const float* csrc = ctrl + (size_t)b * SS * 80 + h * 5;      // +s*80
    float* yptr = ys + (size_t)b * SS * DD + h * HDIM + r;

    unsigned sb_addr[SDEPTH];
#pragma unroll
    for (int d = 0; d < SDEPTH; d++)
        sb_addr[d] = (unsigned)__cvta_generic_to_shared(&sbuf[d][0]);

    // prologue: steps 0..SDEPTH-2 in flight
#pragma unroll
    for (int p = 0; p < SDEPTH - 1; p++) {
        unsigned sa = sb_addr[p & (SDEPTH - 1)];
        const float* bp = bsrc + (size_t)p * 3072;
        if (tid < 64) {
            cpasync4(sa + tid * 4,         bp + tid);
            cpasync4(sa + (64 + tid) * 4,  bp + 64 + tid);
            cpasync4(sa + (128 + tid) * 4, bp + 128 + tid);
        } else if (tid < 69) {
            cpasync4(sa + (192 + tid - 64) * 4, csrc + (size_t)p * 80 + (tid - 64));
        }
        cpcommit();
    }

    for (int s = 0; s < SS; s++) {
        cpwait2();
        __syncthreads();   // stage s visible to all; stage (s-1) reads done

        int pf = s + SDEPTH - 1;
        if (pf < SS) {
            unsigned sa = sb_addr[pf & (SDEPTH - 1)];
            const float* bp = bsrc + (size_t)pf * 3072;
            if (tid < 64) {
                cpasync4(sa + tid * 4,         bp + tid);
                cpasync4(sa + (64 + tid) * 4,  bp + 64 + tid);
                cpasync4(sa + (128 + tid) * 4, bp + 128 + tid);
            } else if (tid < 69) {
                cpasync4(sa + (192 + tid - 64) * 4, csrc + (size_t)pf * 80 + (tid - 64));
            }
        }
        cpcommit();

        const float* sb = sbuf[s & (SDEPTH - 1)];
        float c0 = sb[192], c1 = sb[193], c2 = sb[194];
        float eta   = 1.f / (1.f + __expf(-sb[195]));
        float alpha = 1.f / (1.f + __expf(-sb[196]));

        float kr[16], qr[16];
#pragma unroll
        for (int w = 0; w < 4; w++) {
            *(float4*)&kr[w * 4] = *(const float4*)&sb[g * 16 + w * 4];
            *(float4*)&qr[w * 4] = *(const float4*)&sb[128 + g * 16 + w * 4];
        }
        float dq0 = 0.f, dq1 = 0.f, dk0 = 0.f, dk1 = 0.f;
#pragma unroll
        for (int jj = 0; jj < 16; jj += 2) {
            dq0 += m[jj] * qr[jj];
            dq1 += m[jj + 1] * qr[jj + 1];
            dk0 += m[jj] * kr[jj];
            dk1 += m[jj + 1] * kr[jj + 1];
        }
        float dq = dq0 + dq1, dk = dk0 + dk1;
        dq += __shfl_xor_sync(0xffffffffu, dq, 1);
        dq += __shfl_xor_sync(0xffffffffu, dq, 2);
        dk += __shfl_xor_sync(0xffffffffu, dk, 1);
        dk += __shfl_xor_sync(0xffffffffu, dk, 2);

        float err = c0 * dk - c1 * sb[64 + r];     // (M k) - v
        if (g == 0) yptr[(size_t)s * DD] = c2 * dq;

        float ekc = eta * err * c0;
#pragma unroll
        for (int jj = 0; jj < 16; jj++)
            m[jj] = alpha * m[jj] + ekc * kr[jj];
    }

    float* MF = mfinal + (((size_t)bh * HDIM + r) * HDIM + g * 16);
#pragma unroll
    for (int jj = 0; jj < 16; jj++) MF[jj] = m[jj];
}

// ---------------------------------------------------------------------------
extern "C" void kernel_launch(void* const* d_in, const int* in_sizes, int n_in,
                              void* d_out, int out_size)
{
    (void)in_sizes; (void)n_in;
    const float* x       = (const float*)d_in[0];
    const float* memory0 = (const float*)d_in[1];
    const float* W_in    = (const float*)d_in[2];
    const float* b_in    = (const float*)d_in[3];
    const float* Wc1     = (const float*)d_in[4];
    const float* bc1     = (const float*)d_in[5];
    const float* Wc2     = (const float*)d_in[6];
    const float* bc2     = (const float*)d_in[7];
    const float* W_out   = (const float*)d_in[8];
    const float* b_out   = (const float*)d_in[9];

    float* out = (float*)d_out;

    float *base, *hidden, *ctrl, *ys, *mf_scratch;
    cudaGetSymbolAddress((void**)&base,       g_base);
    cudaGetSymbolAddress((void**)&hidden,     g_hidden);
    cudaGetSymbolAddress((void**)&ctrl,       g_ctrl);
    cudaGetSymbolAddress((void**)&ys,         g_ys);
    cudaGetSymbolAddress((void**)&mf_scratch, g_mf);

    const size_t OUT_ELEMS = (size_t)BB * SS * DD;
    const size_t MF_ELEMS  = (size_t)BB * HH * HDIM * HDIM;
    float* mfinal = ((size_t)out_size >= OUT_ELEMS + MF_ELEMS)
                        ? (out + OUT_ELEMS) : mf_scratch;

    const int Mrows = BB * SS;  // 8192

    gemm_bf16x3<<<dim3(3 * DD / TBN, Mrows / TBM), 256>>>(
        x, W_in, b_in, base, Mrows, 3 * DD, DD, 0);
    gemm_bf16x3<<<dim3(DD / TBN, Mrows / TBM), 256>>>(
        x, Wc1, bc1, hidden, Mrows, DD, DD, 1);
    gemm_bf16x3<<<dim3(1, Mrows / TBM), 256>>>(
        hidden, Wc2, bc2, ctrl, Mrows, 5 * HH, DD, 0);
    scan_kernel<<<BB * HH * 2, 128>>>(base, ctrl, memory0, ys, mfinal);
    gemm_bf16x3<<<dim3(DD / TBN, Mrows / TBM), 256>>>(
        ys, W_out, b_out, out, Mrows, DD, DD, 0);
}